// round 10
// baseline (speedup 1.0000x reference)
#include <cuda_runtime.h>
#include <math.h>

#define T_NODES 32768
#define D_DIM   64
#define B_GR    32
#define NPG     1024
#define CSR_CAP 64

typedef unsigned long long ull;

// ---------------- scratch ----------------
__device__ float   g_h[T_NODES * 64];
__device__ float   g_xlr[T_NODES * 128];   // xl (0..63) | xr (64..127)
__device__ float   g_lbuf[T_NODES * 64];
__device__ int     g_cnt[T_NODES];
__device__ int     g_csr[T_NODES * CSR_CAP];
__device__ float   g_Pg[B_GR];
__device__ float   g_Vg[B_GR];
__device__ unsigned g_vmax[B_GR];
__device__ int     g_is64;
__device__ int     g_done;

__device__ __forceinline__ float lrelu(float v) { return v > 0.f ? v : 0.2f * v; }

__device__ __forceinline__ unsigned enc_f(float f) {
    unsigned u = __float_as_uint(f);
    return (u & 0x80000000u) ? ~u : (u | 0x80000000u);
}
__device__ __forceinline__ float dec_f(unsigned u) {
    u = (u & 0x80000000u) ? (u & 0x7fffffffu) : ~u;
    return __uint_as_float(u);
}

// ---------------- CSR build ----------------
__global__ void k_init(const int* ew) {
    int i = blockIdx.x * blockDim.x + threadIdx.x;
    if (i < T_NODES) g_cnt[i] = 0;
    if (i < B_GR)    g_vmax[i] = 0x007FFFFFu;
    if (i == 0) {
        g_done = 0;
        int z = 1;
        for (int j = 1; j < 256; j += 2) if (ew[j] != 0) { z = 0; break; }
        g_is64 = z;
    }
}

__device__ __forceinline__ int edge_val(const void* ei, long long idx) {
    if (g_is64) return (int)((const long long*)ei)[idx];
    return ((const int*)ei)[idx];
}

__global__ void k_scatter(const void* ei, int E) {
    int i = blockIdx.x * blockDim.x + threadIdx.x;
    if (i >= E) return;
    int s = edge_val(ei, i);
    int d = edge_val(ei, (long long)E + i);
    int pos = atomicAdd(&g_cnt[d], 1);
    if (pos < CSR_CAP) g_csr[d * CSR_CAP + pos] = s;
}

// ---------------- tiled fp32 GEMM: dup-A smem, LDS.128 B, pure FFMA2 mainloop ------
// hdup[f][r] (ull): activation value duplicated into both halves at FILL time ->
//   mainloop A-load is one broadcast LDS.64 that is directly the fma.f32x2 operand.
// wq[f][jj][tx][q] (ull): col-pair (c=8tx+2(2jj+q), c+1) of W row f. Lane tx reads
//   16B at &wq[f][jj][tx][0] -> lane stride 16B, each 8-lane quarter spans all 32
//   banks once: conflict-free LDS.128 yielding 2 FFMA2 B-operands.
// Mainloop per f: 4 LDS.64 + 2 LDS.128 + 16 FFMA2 (RPT=4). No MOVs.
template <int F, int NOUT>
__global__ void k_gemm(const float* in, const float* __restrict__ Wa,
                       const float* __restrict__ Wb, const float* __restrict__ bias) {
    constexpr int TX  = NOUT / 8;
    constexpr int TY  = 256 / TX;
    constexpr int RPT = 64 / TY;
    extern __shared__ ull smem[];
    ull* hdup = smem;                 // F * 64
    ull* wq   = smem + F * 64;        // F * 4 * TX   ([f][jj(2)][tx][q(2)])
    const float* src = in ? in : g_h;
    float* out = (NOUT == 128) ? g_xlr : g_lbuf;
    int row0 = blockIdx.x * 64;
    int tid  = threadIdx.x;

    // hdup fill: r fastest -> conflict-free STS.64; strided LDGs are L1-absorbed
    for (int idx = tid; idx < 64 * F; idx += 256) {
        int r = idx & 63, f = idx >> 6;
        unsigned hv = __float_as_uint(src[(row0 + r) * F + f]);
        ull v;
        asm("mov.b64 %0, {%1, %1};" : "=l"(v) : "r"(hv));
        hdup[f * 64 + r] = v;
    }
    // wq fill: destination-linear -> conflict-free STS.64
    for (int idx = tid; idx < F * 4 * TX; idx += 256) {
        int q  = idx & 1;
        int tx = (idx >> 1) % TX;
        int jj = (idx / (2 * TX)) & 1;
        int f  = idx / (4 * TX);
        int c  = tx * 8 + 2 * (jj * 2 + q);
        float lo, hi;
        if (NOUT == 128 && c >= 64) {
            lo = Wb[(c - 64) * F + f];
            hi = Wb[(c - 63) * F + f];
        } else {
            lo = Wa[c * F + f];
            hi = Wa[(c + 1) * F + f];
        }
        ull v;
        asm("mov.b64 %0, {%1, %2};" : "=l"(v) : "r"(__float_as_uint(lo)), "r"(__float_as_uint(hi)));
        wq[idx] = v;
    }
    __syncthreads();

    int tx = tid % TX, ty = tid / TX;
    ull acc2[RPT][4];
#pragma unroll
    for (int i = 0; i < RPT; i++)
#pragma unroll
        for (int j = 0; j < 4; j++) acc2[i][j] = 0ull;

#pragma unroll 4
    for (int f = 0; f < F; f++) {
        ull aa[RPT];
#pragma unroll
        for (int i = 0; i < RPT; i++) aa[i] = hdup[f * 64 + ty * RPT + i];
        ulonglong2 b01 = *(const ulonglong2*)&wq[((f * 2 + 0) * TX + tx) * 2];
        ulonglong2 b23 = *(const ulonglong2*)&wq[((f * 2 + 1) * TX + tx) * 2];
        ull b2[4] = {b01.x, b01.y, b23.x, b23.y};
#pragma unroll
        for (int i = 0; i < RPT; i++) {
#pragma unroll
            for (int j = 0; j < 4; j++)
                asm("fma.rn.f32x2 %0, %1, %2, %0;" : "+l"(acc2[i][j]) : "l"(aa[i]), "l"(b2[j]));
        }
    }

#pragma unroll
    for (int i = 0; i < RPT; i++) {
        int row = row0 + ty * RPT + i;
        float vals[8];
#pragma unroll
        for (int j = 0; j < 4; j++) {
            unsigned lo, hi;
            asm("mov.b64 {%0, %1}, %2;" : "=r"(lo), "=r"(hi) : "l"(acc2[i][j]));
            vals[2 * j]     = __uint_as_float(lo);
            vals[2 * j + 1] = __uint_as_float(hi);
        }
        if (bias) {
#pragma unroll
            for (int j = 0; j < 8; j++) vals[j] += bias[tx * 8 + j];
        }
        *(float4*)&out[row * NOUT + tx * 8]     = make_float4(vals[0], vals[1], vals[2], vals[3]);
        *(float4*)&out[row * NOUT + tx * 8 + 4] = make_float4(vals[4], vals[5], vals[6], vals[7]);
    }
}

// ---------------- GATv2 aggregation (R7/R8 verbatim) ----------------
__global__ void k_agg(const float* __restrict__ att, const float* __restrict__ bias,
                      int relu_flag) {
    int warp = (blockIdx.x * blockDim.x + threadIdx.x) >> 5;
    if (warp >= T_NODES) return;
    int lane = threadIdx.x & 31;
    int q    = lane >> 3;
    int sub  = lane & 7;
    int dst  = warp;

    const float4* xlr4 = (const float4*)g_xlr;
    float4 xr_a = xlr4[dst * 32 + 16 + sub];
    float4 xr_b = xlr4[dst * 32 + 24 + sub];
    float4 at_a = ((const float4*)att)[sub];
    float4 at_b = ((const float4*)att)[8 + sub];

    int nE = min(g_cnt[dst], CSR_CAP);
    int total = nE + 1;
    const int* row = g_csr + dst * CSR_CAP;

    float s = 0.f;
    float4 accA = make_float4(0.f, 0.f, 0.f, 0.f);
    float4 accB = make_float4(0.f, 0.f, 0.f, 0.f);

    for (int base = 0; base < total; base += 4) {
        int idx = base + q;
        bool valid = idx < total;
        int srcn = dst;
        if (idx < nE) srcn = row[idx];
        float4 xa = xlr4[srcn * 32 + sub];
        float4 xb = xlr4[srcn * 32 + 8 + sub];
        float p = lrelu(xa.x + xr_a.x) * at_a.x
                + lrelu(xa.y + xr_a.y) * at_a.y
                + lrelu(xa.z + xr_a.z) * at_a.z
                + lrelu(xa.w + xr_a.w) * at_a.w
                + lrelu(xb.x + xr_b.x) * at_b.x
                + lrelu(xb.y + xr_b.y) * at_b.y
                + lrelu(xb.z + xr_b.z) * at_b.z
                + lrelu(xb.w + xr_b.w) * at_b.w;
        p += __shfl_xor_sync(0xffffffffu, p, 1);
        p += __shfl_xor_sync(0xffffffffu, p, 2);
        p += __shfl_xor_sync(0xffffffffu, p, 4);
        float c = valid ? __expf(p) : 0.f;
        s += c;
        accA.x = fmaf(c, xa.x, accA.x); accA.y = fmaf(c, xa.y, accA.y);
        accA.z = fmaf(c, xa.z, accA.z); accA.w = fmaf(c, xa.w, accA.w);
        accB.x = fmaf(c, xb.x, accB.x); accB.y = fmaf(c, xb.y, accB.y);
        accB.z = fmaf(c, xb.z, accB.z); accB.w = fmaf(c, xb.w, accB.w);
    }

#pragma unroll
    for (int o = 8; o <= 16; o <<= 1) {
        accA.x += __shfl_xor_sync(0xffffffffu, accA.x, o);
        accA.y += __shfl_xor_sync(0xffffffffu, accA.y, o);
        accA.z += __shfl_xor_sync(0xffffffffu, accA.z, o);
        accA.w += __shfl_xor_sync(0xffffffffu, accA.w, o);
        accB.x += __shfl_xor_sync(0xffffffffu, accB.x, o);
        accB.y += __shfl_xor_sync(0xffffffffu, accB.y, o);
        accB.z += __shfl_xor_sync(0xffffffffu, accB.z, o);
        accB.w += __shfl_xor_sync(0xffffffffu, accB.w, o);
        s += __shfl_xor_sync(0xffffffffu, s, o);
    }

    if (q == 0) {
        float inv = 1.f / s;
        float4 bi_a = ((const float4*)bias)[sub];
        float4 bi_b = ((const float4*)bias)[8 + sub];
        float4 oA, oB;
        oA.x = accA.x * inv + bi_a.x; oA.y = accA.y * inv + bi_a.y;
        oA.z = accA.z * inv + bi_a.z; oA.w = accA.w * inv + bi_a.w;
        oB.x = accB.x * inv + bi_b.x; oB.y = accB.y * inv + bi_b.y;
        oB.z = accB.z * inv + bi_b.z; oB.w = accB.w * inv + bi_b.w;
        if (relu_flag) {
            oA.x = fmaxf(oA.x, 0.f); oA.y = fmaxf(oA.y, 0.f);
            oA.z = fmaxf(oA.z, 0.f); oA.w = fmaxf(oA.w, 0.f);
            oB.x = fmaxf(oB.x, 0.f); oB.y = fmaxf(oB.y, 0.f);
            oB.z = fmaxf(oB.z, 0.f); oB.w = fmaxf(oB.w, 0.f);
        }
        ((float4*)g_h)[dst * 16 + sub]     = oA;
        ((float4*)g_h)[dst * 16 + 8 + sub] = oB;
    }
}

// ---------------- heads ----------------
__global__ void k_pool_graph(const float* __restrict__ t6w, const float* __restrict__ t6b,
                             const float* __restrict__ t5pw, const float* __restrict__ t5vw) {
    int g = blockIdx.x, tid = threadIdx.x;
    int dim = tid & 63, rp = tid >> 6;
    float sum = 0.f;
    for (int r = rp; r < NPG; r += 4) sum += g_h[(g * NPG + r) * 64 + dim];
    __shared__ float sh[256];
    __shared__ float mu[64];
    sh[tid] = sum;
    __syncthreads();
    if (rp == 0)
        mu[dim] = (sh[dim] + sh[64 + dim] + sh[128 + dim] + sh[192 + dim]) * (1.f / (float)NPG);
    __syncthreads();
    if (tid < 64) {
        int d = tid;
        float acc = t6b[d];
        for (int f = 0; f < 64; f++) acc = fmaf(t6w[d * 64 + f], mu[f], acc);
        float r = fmaxf(acc, 0.f);
        __shared__ float sp[64], sv[64];
        sp[d] = r * t5pw[d];
        sv[d] = r * t5vw[d];
        __syncthreads();
        for (int o = 32; o; o >>= 1) {
            if (d < o) { sp[d] += sp[d + o]; sv[d] += sv[d + o]; }
            __syncthreads();
        }
        if (d == 0) { g_Pg[g] = sp[0]; g_Vg[g] = sv[0]; }
    }
}

__global__ void k_final(const int* __restrict__ reach,
                        const float* __restrict__ t5pw, const float* __restrict__ t5vw,
                        const float* __restrict__ t5pb, const float* __restrict__ t5vb,
                        const float* __restrict__ pw, const float* __restrict__ pb,
                        const float* __restrict__ vw, const float* __restrict__ vb,
                        float* __restrict__ out) {
    int warp = (blockIdx.x * blockDim.x + threadIdx.x) >> 5;
    int lane = threadIdx.x & 31;
    if (warp < T_NODES) {
        int t = warp, g = t >> 10;
        float l0 = fmaxf(g_lbuf[t * 64 + lane], 0.f);
        float l1 = fmaxf(g_lbuf[t * 64 + 32 + lane], 0.f);
        float p = l0 * t5pw[64 + lane] + l1 * t5pw[96 + lane];
        float v = l0 * t5vw[64 + lane] + l1 * t5vw[96 + lane];
#pragma unroll
        for (int o = 16; o; o >>= 1) {
            p += __shfl_xor_sync(0xffffffffu, p, o);
            v += __shfl_xor_sync(0xffffffffu, v, o);
        }
        if (lane == 0) {
            out[t] = (g_Pg[g] + p + t5pb[0]) * pw[0] + pb[0];
            float q = g_Vg[g] + v + t5vb[0];
            if (reach[t] == 0) q = -1e20f;
            atomicMax(&g_vmax[g], enc_f(q));
        }
    }
    __syncthreads();
    if (threadIdx.x == 0) {
        __threadfence();
        int ticket = atomicAdd(&g_done, 1);
        if (ticket == (int)gridDim.x - 1) {
            for (int g = 0; g < B_GR; g++)
                out[T_NODES + g] = dec_f(g_vmax[g]) * vw[0] + vb[0];
        }
    }
}

// ---------------- launch ----------------
extern "C" void kernel_launch(void* const* d_in, const int* in_sizes, int n_in,
                              void* d_out, int out_size) {
    const float* x     = (const float*)d_in[0];
    const void*  ei    = d_in[1];
    const int*   reach = (const int*)d_in[2];
    const float* Wl0   = (const float*)d_in[3];
    const float* Wr0   = (const float*)d_in[4];
    const float* att0  = (const float*)d_in[5];
    const float* b0    = (const float*)d_in[6];
    const float* Wl    = (const float*)d_in[7];
    const float* Wr    = (const float*)d_in[8];
    const float* att   = (const float*)d_in[9];
    const float* bb    = (const float*)d_in[10];
    const float* t6w   = (const float*)d_in[11];
    const float* t6b   = (const float*)d_in[12];
    const float* t7w   = (const float*)d_in[13];
    const float* t7b   = (const float*)d_in[14];
    const float* t5pw  = (const float*)d_in[15];
    const float* t5pb  = (const float*)d_in[16];
    const float* t5vw  = (const float*)d_in[17];
    const float* t5vb  = (const float*)d_in[18];
    const float* pw    = (const float*)d_in[19];
    const float* pb    = (const float*)d_in[20];
    const float* vw    = (const float*)d_in[21];
    const float* vb    = (const float*)d_in[22];
    float* out = (float*)d_out;

    int E = in_sizes[1] / 2;

    // dynamic smem sizes (bytes): hdup F*64 ull + wq F*4*TX ull
    const int smem_big  = (64 * 64 + 64 * 4 * 16) * 8;   // 65536
    const int smem_l0   = (8 * 64 + 8 * 4 * 16) * 8;     // 8192
    const int smem_t7   = (64 * 64 + 64 * 4 * 8) * 8;    // 49152

    cudaFuncSetAttribute(k_gemm<64, 128>, cudaFuncAttributeMaxDynamicSharedMemorySize, smem_big);
    cudaFuncSetAttribute(k_gemm<64, 64>,  cudaFuncAttributeMaxDynamicSharedMemorySize, smem_t7);

    k_init<<<(T_NODES + 255) / 256, 256>>>((const int*)ei);
    k_scatter<<<(E + 255) / 256, 256>>>(ei, E);

    k_gemm<8, 128><<<T_NODES / 64, 256, smem_l0>>>(x, Wl0, Wr0, nullptr);
    k_agg<<<T_NODES / 8, 256>>>(att0, b0, 1);

    for (int k = 0; k < 4; k++) {
        k_gemm<64, 128><<<T_NODES / 64, 256, smem_big>>>(nullptr, Wl + k * 4096, Wr + k * 4096, nullptr);
        k_agg<<<T_NODES / 8, 256>>>(att + k * 64, bb + k * 64, (k < 3) ? 1 : 0);
    }

    k_pool_graph<<<B_GR, 256>>>(t6w, t6b, t5pw, t5vw);
    k_gemm<64, 64><<<T_NODES / 64, 256, smem_t7>>>(nullptr, t7w, nullptr, t7b);
    k_final<<<T_NODES / 8, 256>>>(reach, t5pw, t5vw, t5pb, t5vb, pw, pb, vw, vb, out);
}

// round 11
// speedup vs baseline: 1.4142x; 1.4142x over previous
#include <cuda_runtime.h>
#include <math.h>

#define T_NODES 32768
#define D_DIM   64
#define B_GR    32
#define NPG     1024
#define CSR_CAP 64

typedef unsigned long long ull;

// ---------------- scratch ----------------
__device__ float   g_h[T_NODES * 64];
__device__ float   g_xlr[T_NODES * 128];   // xl (0..63) | xr (64..127)
__device__ float   g_lbuf[T_NODES * 64];
__device__ int     g_cnt[T_NODES];
__device__ int     g_csr[T_NODES * CSR_CAP];
__device__ float   g_Pg[B_GR];
__device__ float   g_Vg[B_GR];
__device__ unsigned g_vmax[B_GR];
__device__ int     g_is64;
__device__ int     g_done;

__device__ __forceinline__ float lrelu(float v) { return v > 0.f ? v : 0.2f * v; }

__device__ __forceinline__ unsigned enc_f(float f) {
    unsigned u = __float_as_uint(f);
    return (u & 0x80000000u) ? ~u : (u | 0x80000000u);
}
__device__ __forceinline__ float dec_f(unsigned u) {
    u = (u & 0x80000000u) ? (u & 0x7fffffffu) : ~u;
    return __uint_as_float(u);
}

// ---------------- CSR build ----------------
__global__ void k_init(const int* ew) {
    int i = blockIdx.x * blockDim.x + threadIdx.x;
    if (i < T_NODES) g_cnt[i] = 0;
    if (i < B_GR)    g_vmax[i] = 0x007FFFFFu;
    if (i == 0) {
        g_done = 0;
        int z = 1;
        for (int j = 1; j < 256; j += 2) if (ew[j] != 0) { z = 0; break; }
        g_is64 = z;
    }
}

__device__ __forceinline__ int edge_val(const void* ei, long long idx) {
    if (g_is64) return (int)((const long long*)ei)[idx];
    return ((const int*)ei)[idx];
}

__global__ void k_scatter(const void* ei, int E) {
    int i = blockIdx.x * blockDim.x + threadIdx.x;
    if (i >= E) return;
    int s = edge_val(ei, i);
    int d = edge_val(ei, (long long)E + i);
    int pos = atomicAdd(&g_cnt[d], 1);
    if (pos < CSR_CAP) g_csr[d * CSR_CAP + pos] = s;
}

// ---------------- tiled fp32 GEMM: coalesced fills, FFMA2 mainloop ----------------
// A tile: h_sh[r][f] natural layout, padded row stride HS=F+4. Fill is float4-
//   coalesced (4 lines/warp-request). Mainloop A-read h[r][f] = warp broadcast;
//   pad keeps the (2..4) distinct r-addresses in different banks.
// W tile: wp rows [F][4*TX+1] ull of column pairs (c=8tx+2j, c+1). Fill reads W
//   float4-coalesced; lanes idx^FQ hold rows c / c^1, so 4 shfl_xor assemble the
//   (W[c][f], W[c+1][f]) pairs in-register; even-c lanes store i=0,1, odd-c store
//   i=2,3 (STS.64, <=4-way). Mainloop B-read: bank (2f+2tx)%32 -> conflict-free.
template <int F, int NOUT>
__global__ void k_gemm(const float* in, const float* __restrict__ Wa,
                       const float* __restrict__ Wb, const float* __restrict__ bias) {
    constexpr int TX  = NOUT / 8;
    constexpr int TY  = 256 / TX;
    constexpr int RPT = 64 / TY;
    constexpr int FQ  = F / 4;        // float4 per row of W / h
    constexpr int HS  = F + 4;        // h row stride (floats)
    constexpr int WS  = 4 * TX + 1;   // wp row stride (ull)
    extern __shared__ char smem_raw[];
    float* h_sh = (float*)smem_raw;                               // [64][HS]
    ull*   wp   = (ull*)(smem_raw + 64 * HS * sizeof(float));     // [F][WS]
    const float* src = in ? in : g_h;
    float* out = (NOUT == 128) ? g_xlr : g_lbuf;
    int row0 = blockIdx.x * 64;
    int tid  = threadIdx.x;

    // h fill: fully coalesced float4 read + padded STS.128
    const float4* src4 = (const float4*)(src + (size_t)row0 * F);
    for (int idx = tid; idx < 64 * FQ; idx += 256) {
        int r = idx / FQ, q = idx - r * FQ;
        *(float4*)&h_sh[r * HS + q * 4] = src4[idx];
    }
    // W fill: coalesced float4 read; xor-shfl pairs rows (c, c^1)
    for (int idx = tid; idx < NOUT * FQ; idx += 256) {
        int c = idx / FQ, q = idx - c * FQ;
        float4 myq = (NOUT == 128 && c >= 64) ? ((const float4*)Wb)[idx - 64 * FQ]
                                              : ((const float4*)Wa)[idx];
        float o0 = __shfl_xor_sync(0xffffffffu, myq.x, FQ);
        float o1 = __shfl_xor_sync(0xffffffffu, myq.y, FQ);
        float o2 = __shfl_xor_sync(0xffffffffu, myq.z, FQ);
        float o3 = __shfl_xor_sync(0xffffffffu, myq.w, FQ);
        int c0  = c & ~1;
        int tx_ = c0 >> 3;
        int j_  = (c0 & 7) >> 1;
        float mine[4] = {myq.x, myq.y, myq.z, myq.w};
        float othr[4] = {o0, o1, o2, o3};
        bool even = (c & 1) == 0;
        int i0 = even ? 0 : 2;
#pragma unroll
        for (int ii = 0; ii < 2; ii++) {
            int i = i0 + ii;
            float lo = even ? mine[i] : othr[i];
            float hi = even ? othr[i] : mine[i];
            ull v;
            asm("mov.b64 %0, {%1, %2};" : "=l"(v)
                : "r"(__float_as_uint(lo)), "r"(__float_as_uint(hi)));
            wp[(4 * q + i) * WS + j_ * TX + tx_] = v;
        }
    }
    __syncthreads();

    int tx = tid % TX, ty = tid / TX;
    ull acc2[RPT][4];
#pragma unroll
    for (int i = 0; i < RPT; i++)
#pragma unroll
        for (int j = 0; j < 4; j++) acc2[i][j] = 0ull;

#pragma unroll 4
    for (int f = 0; f < F; f++) {
        float a[RPT];
#pragma unroll
        for (int i = 0; i < RPT; i++) a[i] = h_sh[(ty * RPT + i) * HS + f];
        ull b2[4];
#pragma unroll
        for (int j = 0; j < 4; j++) b2[j] = wp[f * WS + j * TX + tx];
#pragma unroll
        for (int i = 0; i < RPT; i++) {
            ull aa;
            asm("mov.b64 %0, {%1, %1};" : "=l"(aa) : "r"(__float_as_uint(a[i])));
#pragma unroll
            for (int j = 0; j < 4; j++)
                asm("fma.rn.f32x2 %0, %1, %2, %0;" : "+l"(acc2[i][j]) : "l"(aa), "l"(b2[j]));
        }
    }

#pragma unroll
    for (int i = 0; i < RPT; i++) {
        int row = row0 + ty * RPT + i;
        float vals[8];
#pragma unroll
        for (int j = 0; j < 4; j++) {
            unsigned lo, hi;
            asm("mov.b64 {%0, %1}, %2;" : "=r"(lo), "=r"(hi) : "l"(acc2[i][j]));
            vals[2 * j]     = __uint_as_float(lo);
            vals[2 * j + 1] = __uint_as_float(hi);
        }
        if (bias) {
#pragma unroll
            for (int j = 0; j < 8; j++) vals[j] += bias[tx * 8 + j];
        }
        *(float4*)&out[row * NOUT + tx * 8]     = make_float4(vals[0], vals[1], vals[2], vals[3]);
        *(float4*)&out[row * NOUT + tx * 8 + 4] = make_float4(vals[4], vals[5], vals[6], vals[7]);
    }
}

// ---------------- GATv2 aggregation (R8 verbatim) ----------------
__global__ void k_agg(const float* __restrict__ att, const float* __restrict__ bias,
                      int relu_flag) {
    int warp = (blockIdx.x * blockDim.x + threadIdx.x) >> 5;
    if (warp >= T_NODES) return;
    int lane = threadIdx.x & 31;
    int q    = lane >> 3;
    int sub  = lane & 7;
    int dst  = warp;

    const float4* xlr4 = (const float4*)g_xlr;
    float4 xr_a = xlr4[dst * 32 + 16 + sub];
    float4 xr_b = xlr4[dst * 32 + 24 + sub];
    float4 at_a = ((const float4*)att)[sub];
    float4 at_b = ((const float4*)att)[8 + sub];

    int nE = min(g_cnt[dst], CSR_CAP);
    int total = nE + 1;
    const int* row = g_csr + dst * CSR_CAP;

    float s = 0.f;
    float4 accA = make_float4(0.f, 0.f, 0.f, 0.f);
    float4 accB = make_float4(0.f, 0.f, 0.f, 0.f);

    for (int base = 0; base < total; base += 4) {
        int idx = base + q;
        bool valid = idx < total;
        int srcn = dst;
        if (idx < nE) srcn = row[idx];
        float4 xa = xlr4[srcn * 32 + sub];
        float4 xb = xlr4[srcn * 32 + 8 + sub];
        float p = lrelu(xa.x + xr_a.x) * at_a.x
                + lrelu(xa.y + xr_a.y) * at_a.y
                + lrelu(xa.z + xr_a.z) * at_a.z
                + lrelu(xa.w + xr_a.w) * at_a.w
                + lrelu(xb.x + xr_b.x) * at_b.x
                + lrelu(xb.y + xr_b.y) * at_b.y
                + lrelu(xb.z + xr_b.z) * at_b.z
                + lrelu(xb.w + xr_b.w) * at_b.w;
        p += __shfl_xor_sync(0xffffffffu, p, 1);
        p += __shfl_xor_sync(0xffffffffu, p, 2);
        p += __shfl_xor_sync(0xffffffffu, p, 4);
        float c = valid ? __expf(p) : 0.f;
        s += c;
        accA.x = fmaf(c, xa.x, accA.x); accA.y = fmaf(c, xa.y, accA.y);
        accA.z = fmaf(c, xa.z, accA.z); accA.w = fmaf(c, xa.w, accA.w);
        accB.x = fmaf(c, xb.x, accB.x); accB.y = fmaf(c, xb.y, accB.y);
        accB.z = fmaf(c, xb.z, accB.z); accB.w = fmaf(c, xb.w, accB.w);
    }

#pragma unroll
    for (int o = 8; o <= 16; o <<= 1) {
        accA.x += __shfl_xor_sync(0xffffffffu, accA.x, o);
        accA.y += __shfl_xor_sync(0xffffffffu, accA.y, o);
        accA.z += __shfl_xor_sync(0xffffffffu, accA.z, o);
        accA.w += __shfl_xor_sync(0xffffffffu, accA.w, o);
        accB.x += __shfl_xor_sync(0xffffffffu, accB.x, o);
        accB.y += __shfl_xor_sync(0xffffffffu, accB.y, o);
        accB.z += __shfl_xor_sync(0xffffffffu, accB.z, o);
        accB.w += __shfl_xor_sync(0xffffffffu, accB.w, o);
        s += __shfl_xor_sync(0xffffffffu, s, o);
    }

    if (q == 0) {
        float inv = 1.f / s;
        float4 bi_a = ((const float4*)bias)[sub];
        float4 bi_b = ((const float4*)bias)[8 + sub];
        float4 oA, oB;
        oA.x = accA.x * inv + bi_a.x; oA.y = accA.y * inv + bi_a.y;
        oA.z = accA.z * inv + bi_a.z; oA.w = accA.w * inv + bi_a.w;
        oB.x = accB.x * inv + bi_b.x; oB.y = accB.y * inv + bi_b.y;
        oB.z = accB.z * inv + bi_b.z; oB.w = accB.w * inv + bi_b.w;
        if (relu_flag) {
            oA.x = fmaxf(oA.x, 0.f); oA.y = fmaxf(oA.y, 0.f);
            oA.z = fmaxf(oA.z, 0.f); oA.w = fmaxf(oA.w, 0.f);
            oB.x = fmaxf(oB.x, 0.f); oB.y = fmaxf(oB.y, 0.f);
            oB.z = fmaxf(oB.z, 0.f); oB.w = fmaxf(oB.w, 0.f);
        }
        ((float4*)g_h)[dst * 16 + sub]     = oA;
        ((float4*)g_h)[dst * 16 + 8 + sub] = oB;
    }
}

// ---------------- heads ----------------
__global__ void k_pool_graph(const float* __restrict__ t6w, const float* __restrict__ t6b,
                             const float* __restrict__ t5pw, const float* __restrict__ t5vw) {
    int g = blockIdx.x, tid = threadIdx.x;
    int dim = tid & 63, rp = tid >> 6;
    float sum = 0.f;
    for (int r = rp; r < NPG; r += 4) sum += g_h[(g * NPG + r) * 64 + dim];
    __shared__ float sh[256];
    __shared__ float mu[64];
    sh[tid] = sum;
    __syncthreads();
    if (rp == 0)
        mu[dim] = (sh[dim] + sh[64 + dim] + sh[128 + dim] + sh[192 + dim]) * (1.f / (float)NPG);
    __syncthreads();
    if (tid < 64) {
        int d = tid;
        float acc = t6b[d];
        for (int f = 0; f < 64; f++) acc = fmaf(t6w[d * 64 + f], mu[f], acc);
        float r = fmaxf(acc, 0.f);
        __shared__ float sp[64], sv[64];
        sp[d] = r * t5pw[d];
        sv[d] = r * t5vw[d];
        __syncthreads();
        for (int o = 32; o; o >>= 1) {
            if (d < o) { sp[d] += sp[d + o]; sv[d] += sv[d + o]; }
            __syncthreads();
        }
        if (d == 0) { g_Pg[g] = sp[0]; g_Vg[g] = sv[0]; }
    }
}

__global__ void k_final(const int* __restrict__ reach,
                        const float* __restrict__ t5pw, const float* __restrict__ t5vw,
                        const float* __restrict__ t5pb, const float* __restrict__ t5vb,
                        const float* __restrict__ pw, const float* __restrict__ pb,
                        const float* __restrict__ vw, const float* __restrict__ vb,
                        float* __restrict__ out) {
    int warp = (blockIdx.x * blockDim.x + threadIdx.x) >> 5;
    int lane = threadIdx.x & 31;
    if (warp < T_NODES) {
        int t = warp, g = t >> 10;
        float l0 = fmaxf(g_lbuf[t * 64 + lane], 0.f);
        float l1 = fmaxf(g_lbuf[t * 64 + 32 + lane], 0.f);
        float p = l0 * t5pw[64 + lane] + l1 * t5pw[96 + lane];
        float v = l0 * t5vw[64 + lane] + l1 * t5vw[96 + lane];
#pragma unroll
        for (int o = 16; o; o >>= 1) {
            p += __shfl_xor_sync(0xffffffffu, p, o);
            v += __shfl_xor_sync(0xffffffffu, v, o);
        }
        if (lane == 0) {
            out[t] = (g_Pg[g] + p + t5pb[0]) * pw[0] + pb[0];
            float q = g_Vg[g] + v + t5vb[0];
            if (reach[t] == 0) q = -1e20f;
            atomicMax(&g_vmax[g], enc_f(q));
        }
    }
    __syncthreads();
    if (threadIdx.x == 0) {
        __threadfence();
        int ticket = atomicAdd(&g_done, 1);
        if (ticket == (int)gridDim.x - 1) {
            for (int g = 0; g < B_GR; g++)
                out[T_NODES + g] = dec_f(g_vmax[g]) * vw[0] + vb[0];
        }
    }
}

// ---------------- launch ----------------
extern "C" void kernel_launch(void* const* d_in, const int* in_sizes, int n_in,
                              void* d_out, int out_size) {
    const float* x     = (const float*)d_in[0];
    const void*  ei    = d_in[1];
    const int*   reach = (const int*)d_in[2];
    const float* Wl0   = (const float*)d_in[3];
    const float* Wr0   = (const float*)d_in[4];
    const float* att0  = (const float*)d_in[5];
    const float* b0    = (const float*)d_in[6];
    const float* Wl    = (const float*)d_in[7];
    const float* Wr    = (const float*)d_in[8];
    const float* att   = (const float*)d_in[9];
    const float* bb    = (const float*)d_in[10];
    const float* t6w   = (const float*)d_in[11];
    const float* t6b   = (const float*)d_in[12];
    const float* t7w   = (const float*)d_in[13];
    const float* t7b   = (const float*)d_in[14];
    const float* t5pw  = (const float*)d_in[15];
    const float* t5pb  = (const float*)d_in[16];
    const float* t5vw  = (const float*)d_in[17];
    const float* t5vb  = (const float*)d_in[18];
    const float* pw    = (const float*)d_in[19];
    const float* pb    = (const float*)d_in[20];
    const float* vw    = (const float*)d_in[21];
    const float* vb    = (const float*)d_in[22];
    float* out = (float*)d_out;

    int E = in_sizes[1] / 2;

    // dynamic smem bytes: 64*(F+4)*4 (h) + F*(4*TX+1)*8 (wp)
    const int smem_big = 64 * 68 * 4 + 64 * 65 * 8;   // 50688
    const int smem_l0  = 64 * 12 * 4 + 8 * 65 * 8;    // 7232
    const int smem_t7  = 64 * 68 * 4 + 64 * 33 * 8;   // 34304

    cudaFuncSetAttribute(k_gemm<64, 128>, cudaFuncAttributeMaxDynamicSharedMemorySize, smem_big);

    k_init<<<(T_NODES + 255) / 256, 256>>>((const int*)ei);
    k_scatter<<<(E + 255) / 256, 256>>>(ei, E);

    k_gemm<8, 128><<<T_NODES / 64, 256, smem_l0>>>(x, Wl0, Wr0, nullptr);
    k_agg<<<T_NODES / 8, 256>>>(att0, b0, 1);

    for (int k = 0; k < 4; k++) {
        k_gemm<64, 128><<<T_NODES / 64, 256, smem_big>>>(nullptr, Wl + k * 4096, Wr + k * 4096, nullptr);
        k_agg<<<T_NODES / 8, 256>>>(att + k * 64, bb + k * 64, (k < 3) ? 1 : 0);
    }

    k_pool_graph<<<B_GR, 256>>>(t6w, t6b, t5pw, t5vw);
    k_gemm<64, 64><<<T_NODES / 64, 256, smem_t7>>>(nullptr, t7w, nullptr, t7b);
    k_final<<<T_NODES / 8, 256>>>(reach, t5pw, t5vw, t5pb, t5vb, pw, pb, vw, vb, out);
}